// round 13
// baseline (speedup 1.0000x reference)
#include <cuda_runtime.h>

#define M_DIM 1024
#define E_DIM 64
#define S_DIM 2048
#define GS_TOK 8192
#define GEMM_BLOCKS 128      // 64 tokens per block; 32 blocks per group
#define FILL_BLOCKS 2048

__device__ float g_proxy_partial[GEMM_BLOCKS * E_DIM];
__device__ int   g_counts[GEMM_BLOCKS * E_DIM];
__device__ float2 g_sc[GS_TOK];          // {(expert<<6)|local_rank (int bits), gate}
__device__ float g_group_loss[4];
__device__ unsigned int g_loss_cnt;

// ---------------------------------------------------------------------------
// K1: GEMM blocks (GEMM + block-LOCAL rank/count epilogue, no cross-block wait)
//     + fill blocks (EXACT R2 body)
// ---------------------------------------------------------------------------
__global__ __launch_bounds__(256)
void k1_gemm_fill(const float* __restrict__ X, const float* __restrict__ W,
                  float* __restrict__ out, long long out_size)
{
    __shared__ float smem[4160];   // As[64][33]=2112 + Bs[32][64]=2048; L[64][65] overlays
    __shared__ float proxyS[E_DIM];
    __shared__ int   exS[64];
    __shared__ float gateS[64];
    __shared__ int   cntS[128];    // per-32-token-chunk expert counts

    int b = blockIdx.x;
    int tid = threadIdx.x;

    if (b < GEMM_BLOCKS) {
        // ================= GEMM: 64 tokens x 64 experts (EXACT R2 body) =========
        float* As = smem;
        float* Bs = smem + 2112;
        int tx = tid & 15, ty = tid >> 4;
        if (tid < E_DIM) proxyS[tid] = 0.f;
        if (tid < 128) cntS[tid] = 0;

        unsigned long long acc2[4][2];
        #pragma unroll
        for (int i = 0; i < 4; i++) { acc2[i][0] = 0ull; acc2[i][1] = 0ull; }

        int tbase = b * 64;
        const float* Xb = X + (long long)tbase * M_DIM;

        for (int kt = 0; kt < M_DIM; kt += 32) {
            #pragma unroll
            for (int j = 0; j < 2; j++) {
                int t  = (tid >> 3) + j * 32;
                int kq = tid & 7;
                float4 v = *(const float4*)(Xb + (long long)t * M_DIM + kt + kq * 4);
                float* dst = As + t * 33 + kq * 4;
                dst[0] = v.x; dst[1] = v.y; dst[2] = v.z; dst[3] = v.w;
            }
            #pragma unroll
            for (int j = 0; j < 2; j++) {
                int idx = tid + j * 256;
                int r = idx >> 4, c4 = idx & 15;
                ((float4*)Bs)[r * 16 + c4] = ((const float4*)(W + (long long)(kt + r) * E_DIM))[c4];
            }
            __syncthreads();
            #pragma unroll
            for (int kk = 0; kk < 32; kk++) {
                ulonglong2 bq = *((const ulonglong2*)(Bs + kk * 64) + tx);
                #pragma unroll
                for (int i = 0; i < 4; i++) {
                    float a = As[(ty * 4 + i) * 33 + kk];
                    unsigned long long ap;
                    asm("mov.b64 %0, {%1, %1};" : "=l"(ap) : "f"(a));
                    asm("fma.rn.f32x2 %0, %1, %2, %0;" : "+l"(acc2[i][0]) : "l"(ap), "l"(bq.x));
                    asm("fma.rn.f32x2 %0, %1, %2, %0;" : "+l"(acc2[i][1]) : "l"(ap), "l"(bq.y));
                }
            }
            __syncthreads();
        }

        float* L = smem;   // [64][65]
        #pragma unroll
        for (int i = 0; i < 4; i++) {
            float2 v0 = *reinterpret_cast<float2*>(&acc2[i][0]);
            float2 v1 = *reinterpret_cast<float2*>(&acc2[i][1]);
            float* row = L + (ty * 4 + i) * 65 + tx * 4;
            row[0] = v0.x; row[1] = v0.y; row[2] = v1.x; row[3] = v1.y;
        }
        __syncthreads();

        int w = tid >> 5, lane = tid & 31;
        float p0 = 0.f, p1 = 0.f;
        #pragma unroll
        for (int i = 0; i < 8; i++) {
            int row = w * 8 + i;
            float L0 = L[row * 65 + lane];
            float L1 = L[row * 65 + lane + 32];
            float v; int idx;
            if (L0 >= L1) { v = L0; idx = lane; } else { v = L1; idx = lane + 32; }
            #pragma unroll
            for (int off = 16; off; off >>= 1) {
                float ov = __shfl_xor_sync(0xffffffffu, v, off);
                int   oi = __shfl_xor_sync(0xffffffffu, idx, off);
                if (ov > v || (ov == v && oi < idx)) { v = ov; idx = oi; }
            }
            float e0 = expf(L0 - v);
            float e1 = expf(L1 - v);
            float s = e0 + e1;
            #pragma unroll
            for (int off = 16; off; off >>= 1)
                s += __shfl_xor_sync(0xffffffffu, s, off);
            float inv = 1.0f / s;
            p0 += e0 * inv;
            p1 += e1 * inv;
            if (lane == 0) { exS[row] = idx; gateS[row] = inv; }
        }
        atomicAdd(&proxyS[lane], p0);
        atomicAdd(&proxyS[lane + 32], p1);
        __syncthreads();

        // ===== block-LOCAL epilogue: ranks + counts, then retire immediately ====
        int myexp = 0, myrank = 0;
        float mygate = 0.f;
        if (tid < 64) {    // warps 0,1 fully active
            myexp  = exS[tid];
            mygate = gateS[tid];
            unsigned m = __match_any_sync(0xffffffffu, myexp);
            myrank = __popc(m & ((1u << lane) - 1u));
            if (myrank == 0) cntS[(tid >> 5) * 64 + myexp] = __popc(m);
        }
        __syncthreads();
        if (tid < 64) {
            if (tid >= 32) myrank += cntS[myexp];        // add chunk-0 count
            g_counts[b * E_DIM + tid] = cntS[tid] + cntS[64 + tid];
            g_proxy_partial[b * E_DIM + tid] = proxyS[tid];
            g_sc[tbase + tid] = make_float2(__int_as_float((myexp << 6) | myrank), mygate);
        }
        // no fence, no atomic, no wait — k2 is stream-ordered after k1
    } else {
        // ================= zero fill: EXACT R2 body, no additions ================
        long long n4  = out_size >> 2;
        long long fb  = b - GEMM_BLOCKS;
        long long per = n4 / FILL_BLOCKS;
        long long rem = n4 - per * FILL_BLOCKS;
        long long base = fb * per + (fb < rem ? fb : rem);
        if (fb < rem) per++;

        float4 z = make_float4(0.f, 0.f, 0.f, 0.f);
        float4* dst = (float4*)out + base;
        long long i = tid;
        for (; i + 768 < per; i += 1024) {
            __stcs(dst + i,       z);
            __stcs(dst + i + 256, z);
            __stcs(dst + i + 512, z);
            __stcs(dst + i + 768, z);
        }
        for (; i < per; i += 256) __stcs(dst + i, z);

        if (fb == 0) {   // scalar tail incl. aux slot (k2 overwrites aux)
            for (long long t = n4 * 4 + tid; t < out_size; t += 256)
                out[t] = 0.f;
        }
    }
}

// ---------------------------------------------------------------------------
// K2: cross-block offset combine + scatter + aux. 32 blocks x 256 threads.
// Block kb covers tokens kb*256..kb*256+255 (gemm blocks lq*4..lq*4+3 of group g)
// ---------------------------------------------------------------------------
__global__ __launch_bounds__(256)
void k2_combine_scatter(float* __restrict__ out, long long half, int C,
                        long long aux_idx, float aux_scale)
{
    __shared__ int cntAll[32 * E_DIM];   // this group's 32x64 count matrix
    __shared__ int offS[4 * E_DIM];      // exclusive offsets for our 4 gemm blocks
    __shared__ float redS[E_DIM];

    int kb = blockIdx.x;
    int tid = threadIdx.x;
    int g  = kb >> 3;        // group
    int lq = kb & 7;         // quarter: local gemm blocks lq*4 .. lq*4+3

    // prefetch our tokens' packed data (long latency first)
    int tok = kb * 256 + tid;
    float2 sc = g_sc[tok];

    // cooperative load of the whole group's count matrix (coalesced)
    const int* cbase = g_counts + g * 32 * E_DIM;
    #pragma unroll
    for (int j = 0; j < 8; j++) cntAll[j * 256 + tid] = cbase[j * 256 + tid];
    __syncthreads();

    // per-expert prefix over the 32 blocks; stash offsets for our 4 blocks
    if (tid < E_DIM) {
        int run = 0;
        int lb0 = lq * 4;
        #pragma unroll
        for (int bb = 0; bb < 32; bb++) {
            int d = bb - lb0;
            if (d >= 0 && d < 4) offS[d * E_DIM + tid] = run;
            run += cntAll[bb * E_DIM + tid];
        }
        if (lq == 7) {   // has the full per-expert totals -> group aux term
            float proxy = 0.f;
            #pragma unroll
            for (int bb = 0; bb < 32; bb++)
                proxy += g_proxy_partial[(g * 32 + bb) * E_DIM + tid];
            const float invden = 1.0f / (2048.0f * 1.000001f);
            redS[tid] = (proxy * invden) * ((float)run * invden);
        }
    }
    __syncthreads();

    // scatter
    int pk = __float_as_int(sc.x);
    int e  = pk >> 6;
    int r  = pk & 63;
    int pos = offS[(tid >> 6) * E_DIM + e] + r;
    if (pos < C) {
        long long idx = (long long)tok * E_DIM * C + e * C + pos;
        out[idx]        = sc.y;
        out[half + idx] = 1.0f;
    }

    // aux finalize (deterministic fixed-order sums)
    if (lq == 7 && tid < 32) {
        float v = redS[tid] + redS[tid + 32];
        #pragma unroll
        for (int off = 16; off; off >>= 1)
            v += __shfl_xor_sync(0xffffffffu, v, off);
        if (tid == 0) {
            g_group_loss[g] = v;
            __threadfence();
            unsigned p = atomicAdd(&g_loss_cnt, 1u);
            if (p == 3u) {
                __threadfence();
                float a = 0.f;
                for (int gg = 0; gg < 4; gg++) a += g_group_loss[gg];
                out[aux_idx] = a * aux_scale;
                g_loss_cnt = 0;      // reset for next graph replay
            }
        }
    }
}

extern "C" void kernel_launch(void* const* d_in, const int* in_sizes, int n_in,
                              void* d_out, int out_size)
{
    const float* X = (const float*)d_in[0];
    const float* W = (const float*)d_in[1];
    float* out = (float*)d_out;

    long long osz  = (long long)out_size;
    long long half = (osz - 1) / 2;
    int GS = in_sizes[0] / M_DIM;                    // 8192
    int C  = (int)(half / ((long long)GS * E_DIM));  // 160
    int G  = GS / S_DIM;                             // 4
    float aux_scale = (float)((double)E_DIM * E_DIM * 0.01 / ((double)G * E_DIM));

    k1_gemm_fill<<<GEMM_BLOCKS + FILL_BLOCKS, 256>>>(X, W, out, osz);
    k2_combine_scatter<<<GS_TOK / 256, 256>>>(out, half, C, osz - 1, aux_scale);
}

// round 14
// speedup vs baseline: 1.1755x; 1.1755x over previous
#include <cuda_runtime.h>

#define M_DIM 1024
#define E_DIM 64
#define S_DIM 2048
#define GS_TOK 8192
#define GEMM_BLOCKS 128      // 64 tokens per block
#define FILL_BLOCKS 2048

__device__ float g_proxy_partial[GEMM_BLOCKS * E_DIM];
__device__ int   g_expert[GS_TOK];
__device__ float g_gate[GS_TOK];
__device__ float g_group_loss[8];
__device__ unsigned int g_gemm_done;
__device__ unsigned int g_loss_cnt;
__device__ unsigned int g_k2_done;

// ---------------------------------------------------------------------------
// K1: EXACT R2 fill + GEMM; + PDL trigger + GEMM-done counter (R7-validated)
// ---------------------------------------------------------------------------
__global__ __launch_bounds__(256)
void k1_gemm_fill(const float* __restrict__ X, const float* __restrict__ W,
                  float* __restrict__ out, long long out_size)
{
    cudaTriggerProgrammaticLaunchCompletion();

    __shared__ float smem[4160];   // As[64][33]=2112 + Bs[32][64]=2048; L[64][65] overlays
    __shared__ float proxyS[E_DIM];

    int b = blockIdx.x;
    int tid = threadIdx.x;

    if (b < GEMM_BLOCKS) {
        float* As = smem;
        float* Bs = smem + 2112;
        int tx = tid & 15, ty = tid >> 4;
        if (tid < E_DIM) proxyS[tid] = 0.f;

        unsigned long long acc2[4][2];
        #pragma unroll
        for (int i = 0; i < 4; i++) { acc2[i][0] = 0ull; acc2[i][1] = 0ull; }

        int tbase = b * 64;
        const float* Xb = X + (long long)tbase * M_DIM;

        for (int kt = 0; kt < M_DIM; kt += 32) {
            #pragma unroll
            for (int j = 0; j < 2; j++) {
                int t  = (tid >> 3) + j * 32;
                int kq = tid & 7;
                float4 v = *(const float4*)(Xb + (long long)t * M_DIM + kt + kq * 4);
                float* dst = As + t * 33 + kq * 4;
                dst[0] = v.x; dst[1] = v.y; dst[2] = v.z; dst[3] = v.w;
            }
            #pragma unroll
            for (int j = 0; j < 2; j++) {
                int idx = tid + j * 256;
                int r = idx >> 4, c4 = idx & 15;
                ((float4*)Bs)[r * 16 + c4] = ((const float4*)(W + (long long)(kt + r) * E_DIM))[c4];
            }
            __syncthreads();
            #pragma unroll
            for (int kk = 0; kk < 32; kk++) {
                ulonglong2 bq = *((const ulonglong2*)(Bs + kk * 64) + tx);
                #pragma unroll
                for (int i = 0; i < 4; i++) {
                    float a = As[(ty * 4 + i) * 33 + kk];
                    unsigned long long ap;
                    asm("mov.b64 %0, {%1, %1};" : "=l"(ap) : "f"(a));
                    asm("fma.rn.f32x2 %0, %1, %2, %0;" : "+l"(acc2[i][0]) : "l"(ap), "l"(bq.x));
                    asm("fma.rn.f32x2 %0, %1, %2, %0;" : "+l"(acc2[i][1]) : "l"(ap), "l"(bq.y));
                }
            }
            __syncthreads();
        }

        float* L = smem;   // [64][65]
        #pragma unroll
        for (int i = 0; i < 4; i++) {
            float2 v0 = *reinterpret_cast<float2*>(&acc2[i][0]);
            float2 v1 = *reinterpret_cast<float2*>(&acc2[i][1]);
            float* row = L + (ty * 4 + i) * 65 + tx * 4;
            row[0] = v0.x; row[1] = v0.y; row[2] = v1.x; row[3] = v1.y;
        }
        __syncthreads();

        int w = tid >> 5, lane = tid & 31;
        float p0 = 0.f, p1 = 0.f;
        #pragma unroll
        for (int i = 0; i < 8; i++) {
            int row = w * 8 + i;
            float L0 = L[row * 65 + lane];
            float L1 = L[row * 65 + lane + 32];
            float v; int idx;
            if (L0 >= L1) { v = L0; idx = lane; } else { v = L1; idx = lane + 32; }
            #pragma unroll
            for (int off = 16; off; off >>= 1) {
                float ov = __shfl_xor_sync(0xffffffffu, v, off);
                int   oi = __shfl_xor_sync(0xffffffffu, idx, off);
                if (ov > v || (ov == v && oi < idx)) { v = ov; idx = oi; }
            }
            float e0 = expf(L0 - v);
            float e1 = expf(L1 - v);
            float s = e0 + e1;
            #pragma unroll
            for (int off = 16; off; off >>= 1)
                s += __shfl_xor_sync(0xffffffffu, s, off);
            float inv = 1.0f / s;
            p0 += e0 * inv;
            p1 += e1 * inv;
            if (lane == 0) {
                int t = tbase + row;
                g_expert[t] = idx;
                g_gate[t]   = inv;
            }
        }
        atomicAdd(&proxyS[lane], p0);
        atomicAdd(&proxyS[lane + 32], p1);
        __syncthreads();
        if (tid < E_DIM) g_proxy_partial[b * E_DIM + tid] = proxyS[tid];

        // release: signal GEMM completion (128 blocks only; off the fill path)
        __threadfence();
        __syncthreads();
        if (tid == 0) atomicAdd(&g_gemm_done, 1u);
    } else {
        // ================= zero fill: EXACT R2 body, no additions ================
        long long n4  = out_size >> 2;
        long long fb  = b - GEMM_BLOCKS;
        long long per = n4 / FILL_BLOCKS;
        long long rem = n4 - per * FILL_BLOCKS;
        long long base = fb * per + (fb < rem ? fb : rem);
        if (fb < rem) per++;

        float4 z = make_float4(0.f, 0.f, 0.f, 0.f);
        float4* dst = (float4*)out + base;
        long long i = tid;
        for (; i + 768 < per; i += 1024) {
            __stcs(dst + i,       z);
            __stcs(dst + i + 256, z);
            __stcs(dst + i + 512, z);
            __stcs(dst + i + 768, z);
        }
        for (; i < per; i += 256) __stcs(dst + i, z);

        if (fb == 0) {   // scalar tail incl. aux slot (k2 overwrites aux)
            for (long long t = n4 * 4 + tid; t < out_size; t += 256)
                out[t] = 0.f;
        }
    }
}

// ---------------------------------------------------------------------------
// K2 (PDL secondary, 4 x 1024): spin for GEMM -> scan (hidden under fill tail)
// -> gridsync -> scatter (only exposed part) -> aux -> counter reset
// ---------------------------------------------------------------------------
__global__ __launch_bounds__(1024)
void k2_scan_scatter(float* __restrict__ out, long long half, int C,
                     long long aux_idx, float aux_scale, int G)
{
    __shared__ int hist[64 * E_DIM];
    __shared__ unsigned char rank8[S_DIM];
    __shared__ unsigned char ex8[S_DIM];
    __shared__ float redS[E_DIM];

    int g = blockIdx.x;
    int tid = threadIdx.x;
    int lane = tid & 31;
    unsigned lt = (1u << lane) - 1u;

    // wait for GEMM results (done ~40us into k1; we are scheduled ~100us in)
    if (tid == 0)
        while (*(volatile unsigned int*)&g_gemm_done < GEMM_BLOCKS) __nanosleep(64);
    __syncthreads();
    __threadfence();

    for (int i = tid; i < 64 * E_DIM; i += 1024) hist[i] = 0;
    __syncthreads();

    // per-32-token-chunk histogram + in-chunk rank
    #pragma unroll
    for (int h = 0; h < 2; h++) {
        int s = h * 1024 + tid;
        int e = g_expert[g * S_DIM + s];
        unsigned m = __match_any_sync(0xffffffffu, e);
        int r = __popc(m & lt);
        rank8[s] = (unsigned char)r;
        ex8[s]   = (unsigned char)e;
        if (r == 0) hist[(s >> 5) * E_DIM + e] = __popc(m);
    }
    __syncthreads();

    // exclusive prefix over chunks + per-group aux term
    if (tid < E_DIM) {
        int run = 0;
        for (int c = 0; c < 64; c++) {
            int v = hist[c * E_DIM + tid];
            hist[c * E_DIM + tid] = run;
            run += v;
        }
        float proxy = 0.f;
        for (int bb = 0; bb < GEMM_BLOCKS / 4; bb++)
            proxy += g_proxy_partial[(g * (GEMM_BLOCKS / 4) + bb) * E_DIM + tid];
        const float invden = 1.0f / (2048.0f * 1.000001f);
        redS[tid] = (proxy * invden) * ((float)run * invden);
    }
    __syncthreads();
    if (tid < 32) {
        float v = redS[tid] + redS[tid + 32];
        #pragma unroll
        for (int off = 16; off; off >>= 1)
            v += __shfl_xor_sync(0xffffffffu, v, off);
        if (tid == 0) {
            g_group_loss[g] = v;
            __threadfence();
            atomicAdd(&g_loss_cnt, 1u);
        }
    }

    // wait for ALL of k1 (fill included) to complete, then scatter
    cudaGridDependencySynchronize();

    #pragma unroll
    for (int h = 0; h < 2; h++) {
        int s = h * 1024 + tid;
        int e = ex8[s];
        int pos = hist[(s >> 5) * E_DIM + e] + (int)rank8[s];
        int t = g * S_DIM + s;
        if (pos < C) {
            float v = g_gate[t];
            long long idx = ((long long)t * E_DIM + e) * C + pos;
            out[idx]        = v;
            out[half + idx] = 1.0f;
        }
    }

    // aux finalize (deterministic fixed order); co-resident spin is safe
    if (g == 0 && tid == 0) {
        while (*(volatile unsigned int*)&g_loss_cnt < (unsigned)G) __nanosleep(64);
        __threadfence();
        float a = 0.f;
        for (int gg = 0; gg < G; gg++) a += g_group_loss[gg];
        out[aux_idx] = a * aux_scale;
    }

    // last k2 block resets all counters for the next graph replay
    __syncthreads();
    if (tid == 0) {
        unsigned p = atomicAdd(&g_k2_done, 1u);
        if (p == (unsigned)G - 1) {
            g_gemm_done = 0;
            g_loss_cnt  = 0;
            g_k2_done   = 0;
            __threadfence();
        }
    }
}

extern "C" void kernel_launch(void* const* d_in, const int* in_sizes, int n_in,
                              void* d_out, int out_size)
{
    const float* X = (const float*)d_in[0];
    const float* W = (const float*)d_in[1];
    float* out = (float*)d_out;

    long long osz  = (long long)out_size;
    long long half = (osz - 1) / 2;
    int GS = in_sizes[0] / M_DIM;                    // 8192
    int C  = (int)(half / ((long long)GS * E_DIM));  // 160
    int G  = GS / S_DIM;                             // 4
    float aux_scale = (float)((double)E_DIM * E_DIM * 0.01 / ((double)G * E_DIM));

    k1_gemm_fill<<<GEMM_BLOCKS + FILL_BLOCKS, 256>>>(X, W, out, osz);

    // PDL secondary: may begin while k1 is still filling
    cudaLaunchConfig_t cfg = {};
    cfg.gridDim  = dim3((unsigned)G, 1, 1);
    cfg.blockDim = dim3(1024, 1, 1);
    cfg.dynamicSmemBytes = 0;
    cfg.stream = 0;
    cudaLaunchAttribute attr[1];
    attr[0].id = cudaLaunchAttributeProgrammaticStreamSerialization;
    attr[0].val.programmaticStreamSerializationAllowed = 1;
    cfg.attrs = attr;
    cfg.numAttrs = 1;
    cudaLaunchKernelEx(&cfg, k2_scan_scatter, out, half, C, osz - 1, aux_scale, G);
}

// round 15
// speedup vs baseline: 1.1896x; 1.0120x over previous
#include <cuda_runtime.h>

#define M_DIM 1024
#define E_DIM 64
#define S_DIM 2048
#define GS_TOK 8192
#define GEMM_BLOCKS 128      // 64 tokens per block
#define FILL_BLOCKS 2048

__device__ float g_proxy_partial[GEMM_BLOCKS * E_DIM];
__device__ int   g_expert[GS_TOK];
__device__ float g_gate[GS_TOK];
__device__ float g_group_loss[4];
__device__ unsigned int g_loss_cnt;

// ---------------------------------------------------------------------------
// K1: EXACT R2 best — fused zero-fill + gating GEMM (f32x2 FFMA) + softmax
// ---------------------------------------------------------------------------
__global__ __launch_bounds__(256)
void k1_gemm_fill(const float* __restrict__ X, const float* __restrict__ W,
                  float* __restrict__ out, long long out_size)
{
    __shared__ float smem[4160];   // As[64][33]=2112 + Bs[32][64]=2048; L[64][65] overlays
    __shared__ float proxyS[E_DIM];

    int b = blockIdx.x;
    int tid = threadIdx.x;

    if (b < GEMM_BLOCKS) {
        float* As = smem;
        float* Bs = smem + 2112;
        int tx = tid & 15, ty = tid >> 4;
        if (tid < E_DIM) proxyS[tid] = 0.f;

        unsigned long long acc2[4][2];
        #pragma unroll
        for (int i = 0; i < 4; i++) { acc2[i][0] = 0ull; acc2[i][1] = 0ull; }

        int tbase = b * 64;
        const float* Xb = X + (long long)tbase * M_DIM;

        for (int kt = 0; kt < M_DIM; kt += 32) {
            #pragma unroll
            for (int j = 0; j < 2; j++) {
                int t  = (tid >> 3) + j * 32;
                int kq = tid & 7;
                float4 v = *(const float4*)(Xb + (long long)t * M_DIM + kt + kq * 4);
                float* dst = As + t * 33 + kq * 4;
                dst[0] = v.x; dst[1] = v.y; dst[2] = v.z; dst[3] = v.w;
            }
            #pragma unroll
            for (int j = 0; j < 2; j++) {
                int idx = tid + j * 256;
                int r = idx >> 4, c4 = idx & 15;
                ((float4*)Bs)[r * 16 + c4] = ((const float4*)(W + (long long)(kt + r) * E_DIM))[c4];
            }
            __syncthreads();
            #pragma unroll
            for (int kk = 0; kk < 32; kk++) {
                ulonglong2 bq = *((const ulonglong2*)(Bs + kk * 64) + tx);
                #pragma unroll
                for (int i = 0; i < 4; i++) {
                    float a = As[(ty * 4 + i) * 33 + kk];
                    unsigned long long ap;
                    asm("mov.b64 %0, {%1, %1};" : "=l"(ap) : "f"(a));
                    asm("fma.rn.f32x2 %0, %1, %2, %0;" : "+l"(acc2[i][0]) : "l"(ap), "l"(bq.x));
                    asm("fma.rn.f32x2 %0, %1, %2, %0;" : "+l"(acc2[i][1]) : "l"(ap), "l"(bq.y));
                }
            }
            __syncthreads();
        }

        float* L = smem;   // [64][65]
        #pragma unroll
        for (int i = 0; i < 4; i++) {
            float2 v0 = *reinterpret_cast<float2*>(&acc2[i][0]);
            float2 v1 = *reinterpret_cast<float2*>(&acc2[i][1]);
            float* row = L + (ty * 4 + i) * 65 + tx * 4;
            row[0] = v0.x; row[1] = v0.y; row[2] = v1.x; row[3] = v1.y;
        }
        __syncthreads();

        int w = tid >> 5, lane = tid & 31;
        float p0 = 0.f, p1 = 0.f;
        #pragma unroll
        for (int i = 0; i < 8; i++) {
            int row = w * 8 + i;
            float L0 = L[row * 65 + lane];
            float L1 = L[row * 65 + lane + 32];
            float v; int idx;
            if (L0 >= L1) { v = L0; idx = lane; } else { v = L1; idx = lane + 32; }
            #pragma unroll
            for (int off = 16; off; off >>= 1) {
                float ov = __shfl_xor_sync(0xffffffffu, v, off);
                int   oi = __shfl_xor_sync(0xffffffffu, idx, off);
                if (ov > v || (ov == v && oi < idx)) { v = ov; idx = oi; }
            }
            float e0 = expf(L0 - v);
            float e1 = expf(L1 - v);
            float s = e0 + e1;
            #pragma unroll
            for (int off = 16; off; off >>= 1)
                s += __shfl_xor_sync(0xffffffffu, s, off);
            float inv = 1.0f / s;
            p0 += e0 * inv;
            p1 += e1 * inv;
            if (lane == 0) {
                int t = tbase + row;
                g_expert[t] = idx;
                g_gate[t]   = inv;
            }
        }
        atomicAdd(&proxyS[lane], p0);
        atomicAdd(&proxyS[lane + 32], p1);
        __syncthreads();
        if (tid < E_DIM) g_proxy_partial[b * E_DIM + tid] = proxyS[tid];
    } else {
        long long n4  = out_size >> 2;
        long long fb  = b - GEMM_BLOCKS;
        long long per = n4 / FILL_BLOCKS;
        long long rem = n4 - per * FILL_BLOCKS;
        long long base = fb * per + (fb < rem ? fb : rem);
        if (fb < rem) per++;

        float4 z = make_float4(0.f, 0.f, 0.f, 0.f);
        float4* dst = (float4*)out + base;
        long long i = tid;
        for (; i + 768 < per; i += 1024) {
            __stcs(dst + i,       z);
            __stcs(dst + i + 256, z);
            __stcs(dst + i + 512, z);
            __stcs(dst + i + 768, z);
        }
        for (; i < per; i += 256) __stcs(dst + i, z);

        if (fb == 0) {   // scalar tail incl. aux slot (k2 overwrites aux)
            for (long long t = n4 * 4 + tid; t < out_size; t += 256)
                out[t] = 0.f;
        }
    }
}

// ---------------------------------------------------------------------------
// K2: 32 blocks x 256 thr. Block (g, lq) handles tokens [lq*256, lq*256+256)
// of group g: redundant prior-histogram + own-segment ranks -> scatter + aux.
// ---------------------------------------------------------------------------
__global__ __launch_bounds__(256)
void k2_scan_scatter(float* __restrict__ out, long long half, int C,
                     long long aux_idx, float aux_scale)
{
    __shared__ int histS[E_DIM];       // counts of tokens BEFORE this segment
    __shared__ int cntSeg[8 * E_DIM];  // per-32-chunk counts within segment
    __shared__ int offSeg[8 * E_DIM];  // exclusive chunk prefix within segment
    __shared__ float redS[E_DIM];

    int kb = blockIdx.x;
    int tid = threadIdx.x;
    int g  = kb >> 3;      // group
    int lq = kb & 7;       // segment within group
    int lane = tid & 31;
    unsigned lt = (1u << lane) - 1u;

    // prefetch own token data (long latency first)
    int tok = g * S_DIM + lq * 256 + tid;
    int   e    = g_expert[tok];
    float gate = g_gate[tok];

    if (tid < E_DIM) histS[tid] = 0;
    for (int i = tid; i < 8 * E_DIM; i += 256) cntSeg[i] = 0;
    __syncthreads();

    // histogram of the lq*256 prior tokens (warp rounds are 32-aligned chunks)
    int pr = lq * 256;
    for (int i = tid; i < pr; i += 256) {
        int pe = g_expert[g * S_DIM + i];
        unsigned m = __match_any_sync(0xffffffffu, pe);
        if ((m & lt) == 0) atomicAdd(&histS[pe], __popc(m));
    }

    // own-segment chunk counts + in-chunk rank
    int c = tid >> 5;
    unsigned m = __match_any_sync(0xffffffffu, e);
    int r = __popc(m & lt);
    if (r == 0) cntSeg[c * E_DIM + e] = __popc(m);
    __syncthreads();

    // exclusive prefix over the 8 chunks (one thread per expert)
    if (tid < E_DIM) {
        int run = 0;
        #pragma unroll
        for (int cc = 0; cc < 8; cc++) {
            offSeg[cc * E_DIM + tid] = run;
            run += cntSeg[cc * E_DIM + tid];
        }
    }
    __syncthreads();

    // final position + capacity drop + scatter
    int pos = histS[e] + offSeg[c * E_DIM + e] + r;
    if (pos < C) {
        long long idx = (long long)tok * (E_DIM * C) + e * C + pos;
        out[idx]        = gate;
        out[half + idx] = 1.0f;
    }

    // aux: lq==7 blocks hold full group totals
    if (lq == 7) {
        if (tid < E_DIM) {
            float proxy = 0.f;
            #pragma unroll 4
            for (int bb = 0; bb < 32; bb++)
                proxy += g_proxy_partial[(g * 32 + bb) * E_DIM + tid];
            int run = histS[tid] + offSeg[7 * E_DIM + tid] + cntSeg[7 * E_DIM + tid];
            const float invden = 1.0f / (2048.0f * 1.000001f);
            redS[tid] = (proxy * invden) * ((float)run * invden);
        }
        __syncthreads();
        if (tid < 32) {
            float v = redS[tid] + redS[tid + 32];
            #pragma unroll
            for (int off = 16; off; off >>= 1)
                v += __shfl_xor_sync(0xffffffffu, v, off);
            if (tid == 0) {
                g_group_loss[g] = v;
                __threadfence();
                unsigned p = atomicAdd(&g_loss_cnt, 1u);
                if (p == 3u) {                 // last group finalizes (co-resident)
                    __threadfence();
                    float a = 0.f;
                    for (int gg = 0; gg < 4; gg++) a += g_group_loss[gg];
                    out[aux_idx] = a * aux_scale;
                    g_loss_cnt = 0;            // reset for next graph replay
                }
            }
        }
    }
}

extern "C" void kernel_launch(void* const* d_in, const int* in_sizes, int n_in,
                              void* d_out, int out_size)
{
    const float* X = (const float*)d_in[0];
    const float* W = (const float*)d_in[1];
    float* out = (float*)d_out;

    long long osz  = (long long)out_size;
    long long half = (osz - 1) / 2;
    int GS = in_sizes[0] / M_DIM;                    // 8192
    int C  = (int)(half / ((long long)GS * E_DIM));  // 160
    int G  = GS / S_DIM;                             // 4
    float aux_scale = (float)((double)E_DIM * E_DIM * 0.01 / ((double)G * E_DIM));

    k1_gemm_fill<<<GEMM_BLOCKS + FILL_BLOCKS, 256>>>(X, W, out, osz);
    k2_scan_scatter<<<GS_TOK / 256, 256>>>(out, half, C, osz - 1, aux_scale);
}

// round 16
// speedup vs baseline: 1.2046x; 1.0126x over previous
#include <cuda_runtime.h>

#define M_DIM 1024
#define E_DIM 64
#define S_DIM 2048
#define GS_TOK 8192
#define GEMM_BLOCKS 128      // 64 tokens per block
#define FILL_BLOCKS 2048

__device__ float g_proxy_partial[GEMM_BLOCKS * E_DIM];
__device__ int   g_expert[GS_TOK];
__device__ float g_gate[GS_TOK];
__device__ float g_group_loss[4];
__device__ unsigned int g_loss_cnt;

// ---------------------------------------------------------------------------
// K1: EXACT R2 best — fused zero-fill + gating GEMM (f32x2 FFMA) + softmax
// ---------------------------------------------------------------------------
__global__ __launch_bounds__(256)
void k1_gemm_fill(const float* __restrict__ X, const float* __restrict__ W,
                  float* __restrict__ out, long long out_size)
{
    __shared__ float smem[4160];   // As[64][33]=2112 + Bs[32][64]=2048; L[64][65] overlays
    __shared__ float proxyS[E_DIM];

    int b = blockIdx.x;
    int tid = threadIdx.x;

    if (b < GEMM_BLOCKS) {
        float* As = smem;
        float* Bs = smem + 2112;
        int tx = tid & 15, ty = tid >> 4;
        if (tid < E_DIM) proxyS[tid] = 0.f;

        unsigned long long acc2[4][2];
        #pragma unroll
        for (int i = 0; i < 4; i++) { acc2[i][0] = 0ull; acc2[i][1] = 0ull; }

        int tbase = b * 64;
        const float* Xb = X + (long long)tbase * M_DIM;

        for (int kt = 0; kt < M_DIM; kt += 32) {
            #pragma unroll
            for (int j = 0; j < 2; j++) {
                int t  = (tid >> 3) + j * 32;
                int kq = tid & 7;
                float4 v = *(const float4*)(Xb + (long long)t * M_DIM + kt + kq * 4);
                float* dst = As + t * 33 + kq * 4;
                dst[0] = v.x; dst[1] = v.y; dst[2] = v.z; dst[3] = v.w;
            }
            #pragma unroll
            for (int j = 0; j < 2; j++) {
                int idx = tid + j * 256;
                int r = idx >> 4, c4 = idx & 15;
                ((float4*)Bs)[r * 16 + c4] = ((const float4*)(W + (long long)(kt + r) * E_DIM))[c4];
            }
            __syncthreads();
            #pragma unroll
            for (int kk = 0; kk < 32; kk++) {
                ulonglong2 bq = *((const ulonglong2*)(Bs + kk * 64) + tx);
                #pragma unroll
                for (int i = 0; i < 4; i++) {
                    float a = As[(ty * 4 + i) * 33 + kk];
                    unsigned long long ap;
                    asm("mov.b64 %0, {%1, %1};" : "=l"(ap) : "f"(a));
                    asm("fma.rn.f32x2 %0, %1, %2, %0;" : "+l"(acc2[i][0]) : "l"(ap), "l"(bq.x));
                    asm("fma.rn.f32x2 %0, %1, %2, %0;" : "+l"(acc2[i][1]) : "l"(ap), "l"(bq.y));
                }
            }
            __syncthreads();
        }

        float* L = smem;   // [64][65]
        #pragma unroll
        for (int i = 0; i < 4; i++) {
            float2 v0 = *reinterpret_cast<float2*>(&acc2[i][0]);
            float2 v1 = *reinterpret_cast<float2*>(&acc2[i][1]);
            float* row = L + (ty * 4 + i) * 65 + tx * 4;
            row[0] = v0.x; row[1] = v0.y; row[2] = v1.x; row[3] = v1.y;
        }
        __syncthreads();

        int w = tid >> 5, lane = tid & 31;
        float p0 = 0.f, p1 = 0.f;
        #pragma unroll
        for (int i = 0; i < 8; i++) {
            int row = w * 8 + i;
            float L0 = L[row * 65 + lane];
            float L1 = L[row * 65 + lane + 32];
            float v; int idx;
            if (L0 >= L1) { v = L0; idx = lane; } else { v = L1; idx = lane + 32; }
            #pragma unroll
            for (int off = 16; off; off >>= 1) {
                float ov = __shfl_xor_sync(0xffffffffu, v, off);
                int   oi = __shfl_xor_sync(0xffffffffu, idx, off);
                if (ov > v || (ov == v && oi < idx)) { v = ov; idx = oi; }
            }
            float e0 = expf(L0 - v);
            float e1 = expf(L1 - v);
            float s = e0 + e1;
            #pragma unroll
            for (int off = 16; off; off >>= 1)
                s += __shfl_xor_sync(0xffffffffu, s, off);
            float inv = 1.0f / s;
            p0 += e0 * inv;
            p1 += e1 * inv;
            if (lane == 0) {
                int t = tbase + row;
                g_expert[t] = idx;
                g_gate[t]   = inv;
            }
        }
        atomicAdd(&proxyS[lane], p0);
        atomicAdd(&proxyS[lane + 32], p1);
        __syncthreads();
        if (tid < E_DIM) g_proxy_partial[b * E_DIM + tid] = proxyS[tid];
    } else {
        long long n4  = out_size >> 2;
        long long fb  = b - GEMM_BLOCKS;
        long long per = n4 / FILL_BLOCKS;
        long long rem = n4 - per * FILL_BLOCKS;
        long long base = fb * per + (fb < rem ? fb : rem);
        if (fb < rem) per++;

        float4 z = make_float4(0.f, 0.f, 0.f, 0.f);
        float4* dst = (float4*)out + base;
        long long i = tid;
        for (; i + 768 < per; i += 1024) {
            __stcs(dst + i,       z);
            __stcs(dst + i + 256, z);
            __stcs(dst + i + 512, z);
            __stcs(dst + i + 768, z);
        }
        for (; i < per; i += 256) __stcs(dst + i, z);

        if (fb == 0) {   // scalar tail incl. aux slot (k2 overwrites aux)
            for (long long t = n4 * 4 + tid; t < out_size; t += 256)
                out[t] = 0.f;
        }
    }
}

// ---------------------------------------------------------------------------
// K2: 32 blocks x 256 thr. Block (g, lq) handles tokens [lq*256, lq*256+256)
// of group g. Prior-histogram with BATCHED prefetch (one latency window).
// ---------------------------------------------------------------------------
__global__ __launch_bounds__(256)
void k2_scan_scatter(float* __restrict__ out, long long half, int C,
                     long long aux_idx, float aux_scale)
{
    __shared__ int histS[E_DIM];       // counts of tokens BEFORE this segment
    __shared__ int cntSeg[8 * E_DIM];  // per-32-chunk counts within segment
    __shared__ int offSeg[8 * E_DIM];  // exclusive chunk prefix within segment
    __shared__ float redS[E_DIM];

    int kb = blockIdx.x;
    int tid = threadIdx.x;
    int g  = kb >> 3;      // group
    int lq = kb & 7;       // segment within group
    int lane = tid & 31;
    unsigned lt = (1u << lane) - 1u;

    // ---- issue ALL global loads up-front (one latency window, MLP high) ----
    int tok = g * S_DIM + lq * 256 + tid;
    int   e    = g_expert[tok];
    float gate = g_gate[tok];

    int pe[7];
    #pragma unroll
    for (int j = 0; j < 7; j++)
        if (j < lq) pe[j] = g_expert[g * S_DIM + j * 256 + tid];

    float proxy = 0.f;
    if (lq == 7 && tid < E_DIM) {     // aux proxy loads overlap the match rounds
        #pragma unroll 8
        for (int bb = 0; bb < 32; bb++)
            proxy += g_proxy_partial[(g * 32 + bb) * E_DIM + tid];
    }

    if (tid < E_DIM) histS[tid] = 0;
    #pragma unroll
    for (int i = 0; i < 2; i++) cntSeg[i * 256 + tid] = 0;
    __syncthreads();

    // ---- prior-segment histogram: pure match+atomic rounds (no load deps) ----
    #pragma unroll
    for (int j = 0; j < 7; j++) {
        if (j < lq) {                  // lq uniform across warp -> safe
            unsigned m = __match_any_sync(0xffffffffu, pe[j]);
            if ((m & lt) == 0) atomicAdd(&histS[pe[j]], __popc(m));
        }
    }

    // ---- own-segment chunk counts + in-chunk rank ----
    int c = tid >> 5;
    unsigned m = __match_any_sync(0xffffffffu, e);
    int r = __popc(m & lt);
    if (r == 0) cntSeg[c * E_DIM + e] = __popc(m);
    __syncthreads();

    // exclusive prefix over the 8 chunks (one thread per expert)
    if (tid < E_DIM) {
        int run = 0;
        #pragma unroll
        for (int cc = 0; cc < 8; cc++) {
            offSeg[cc * E_DIM + tid] = run;
            run += cntSeg[cc * E_DIM + tid];
        }
    }
    __syncthreads();

    // ---- final position + capacity drop + scatter ----
    int pos = histS[e] + offSeg[c * E_DIM + e] + r;
    if (pos < C) {
        long long idx = (long long)tok * (E_DIM * C) + e * C + pos;
        out[idx]        = gate;
        out[half + idx] = 1.0f;
    }

    // ---- aux: lq==7 blocks hold full group totals ----
    if (lq == 7) {
        if (tid < E_DIM) {
            int run = histS[tid] + offSeg[7 * E_DIM + tid] + cntSeg[7 * E_DIM + tid];
            const float invden = 1.0f / (2048.0f * 1.000001f);
            redS[tid] = (proxy * invden) * ((float)run * invden);
        }
        __syncthreads();
        if (tid < 32) {
            float v = redS[tid] + redS[tid + 32];
            #pragma unroll
            for (int off = 16; off; off >>= 1)
                v += __shfl_xor_sync(0xffffffffu, v, off);
            if (tid == 0) {
                g_group_loss[g] = v;
                __threadfence();
                unsigned p = atomicAdd(&g_loss_cnt, 1u);
                if (p == 3u) {                 // last group finalizes (co-resident)
                    __threadfence();
                    float a = 0.f;
                    for (int gg = 0; gg < 4; gg++) a += g_group_loss[gg];
                    out[aux_idx] = a * aux_scale;
                    g_loss_cnt = 0;            // reset for next graph replay
                }
            }
        }
    }
}

extern "C" void kernel_launch(void* const* d_in, const int* in_sizes, int n_in,
                              void* d_out, int out_size)
{
    const float* X = (const float*)d_in[0];
    const float* W = (const float*)d_in[1];
    float* out = (float*)d_out;

    long long osz  = (long long)out_size;
    long long half = (osz - 1) / 2;
    int GS = in_sizes[0] / M_DIM;                    // 8192
    int C  = (int)(half / ((long long)GS * E_DIM));  // 160
    int G  = GS / S_DIM;                             // 4
    float aux_scale = (float)((double)E_DIM * E_DIM * 0.01 / ((double)G * E_DIM));

    k1_gemm_fill<<<GEMM_BLOCKS + FILL_BLOCKS, 256>>>(X, W, out, osz);
    k2_scan_scatter<<<GS_TOK / 256, 256>>>(out, half, C, osz - 1, aux_scale);
}